// round 2
// baseline (speedup 1.0000x reference)
#include <cuda_runtime.h>
#include <cstdint>

#define NNODES 100000
#define D      256
#define HID    256

// Scratch: per-node partial activations (allocation-free rule -> device globals)
__device__ float g_A[(size_t)NNODES * HID];
__device__ float g_B[(size_t)NNODES * HID];

// ---------------------------------------------------------------------------
// Node GEMM: Out[M, 256] = X[M, 256] @ W[256, 256]   (fp32, SIMT tiled)
// which == 0 -> g_A, which == 1 -> g_B
// 128x128 block tile, BK=16, 256 threads, 8x8 per thread.
// ---------------------------------------------------------------------------
__global__ __launch_bounds__(256, 2)
void node_gemm_kernel(const float* __restrict__ X,
                      const float* __restrict__ W,
                      int M, int which)
{
    const int BM = 128, BN = 128, BK = 16;
    __shared__ float sA[BK][BM];      // transposed X tile: sA[k][m]
    __shared__ float sB[BK][BN];      // W tile: sB[k][n]

    float* __restrict__ Out = which ? g_B : g_A;

    const int tid = threadIdx.x;
    const int tx  = tid & 15;         // n-group 0..15
    const int ty  = tid >> 4;         // m-group 0..15
    const int bm  = blockIdx.y * BM;
    const int bn  = blockIdx.x * BN;

    float acc[8][8];
    #pragma unroll
    for (int i = 0; i < 8; i++)
        #pragma unroll
        for (int j = 0; j < 8; j++)
            acc[i][j] = 0.f;

    for (int k0 = 0; k0 < D; k0 += BK) {
        // --- load X tile (128 rows x 16 cols) as float4, store transposed ---
        #pragma unroll
        for (int l = 0; l < 2; l++) {
            int f   = tid + l * 256;        // float4 index 0..511
            int row = f >> 2;               // 0..127
            int col = (f & 3) << 2;         // 0,4,8,12
            float4 v = make_float4(0.f, 0.f, 0.f, 0.f);
            int gr = bm + row;
            if (gr < M)
                v = *reinterpret_cast<const float4*>(X + (size_t)gr * D + k0 + col);
            sA[col + 0][row] = v.x;
            sA[col + 1][row] = v.y;
            sA[col + 2][row] = v.z;
            sA[col + 3][row] = v.w;
        }
        // --- load W tile (16 rows x 128 cols) as float4, natural layout ---
        #pragma unroll
        for (int l = 0; l < 2; l++) {
            int f   = tid + l * 256;
            int row = f >> 5;               // 0..15
            int col = (f & 31) << 2;        // 0..124
            *reinterpret_cast<float4*>(&sB[row][col]) =
                *reinterpret_cast<const float4*>(W + (size_t)(k0 + row) * HID + bn + col);
        }
        __syncthreads();

        #pragma unroll
        for (int k = 0; k < BK; k++) {
            float a[8], b[8];
            *reinterpret_cast<float4*>(a)     = *reinterpret_cast<float4*>(&sA[k][ty * 8]);
            *reinterpret_cast<float4*>(a + 4) = *reinterpret_cast<float4*>(&sA[k][ty * 8 + 4]);
            *reinterpret_cast<float4*>(b)     = *reinterpret_cast<float4*>(&sB[k][tx * 8]);
            *reinterpret_cast<float4*>(b + 4) = *reinterpret_cast<float4*>(&sB[k][tx * 8 + 4]);
            #pragma unroll
            for (int i = 0; i < 8; i++)
                #pragma unroll
                for (int j = 0; j < 8; j++)
                    acc[i][j] = fmaf(a[i], b[j], acc[i][j]);
        }
        __syncthreads();
    }

    // --- store ---
    #pragma unroll
    for (int i = 0; i < 8; i++) {
        int gr = bm + ty * 8 + i;
        if (gr < M) {
            #pragma unroll
            for (int j = 0; j < 8; j += 4)
                *reinterpret_cast<float4*>(Out + (size_t)gr * HID + bn + tx * 8 + j) =
                    *reinterpret_cast<float4*>(&acc[i][j]);
        }
    }
}

// ---------------------------------------------------------------------------
// Edge scoring: warp per edge slot.
// slot < E  -> pos edge from edge_index;  slot >= E -> neg edge.
// score = sum_h relu(A[s,h] + B[d,h] + b1[h]) * W2[h] + b2
// Indices are int32 (jax x64 disabled downgrades the requested int64).
// Clamp defensively: no-op when valid, converts a dtype mistake into a
// rel_err signal instead of an illegal access.
// ---------------------------------------------------------------------------
__device__ __forceinline__ int clamp_idx(int v) {
    v = v < 0 ? 0 : v;
    return v >= NNODES ? NNODES - 1 : v;
}

__global__ __launch_bounds__(256)
void edge_score_kernel(const int* __restrict__ ei,
                       const int* __restrict__ nei,
                       const float* __restrict__ b1,
                       const float* __restrict__ W2,
                       const float* __restrict__ b2,
                       float* __restrict__ out,
                       int E)
{
    const int lane = threadIdx.x & 31;
    const int warp = (blockIdx.x * blockDim.x + threadIdx.x) >> 5;
    if (warp >= 2 * E) return;

    // b1/W2 per-lane constants (same h-set for every edge this lane touches)
    float rb1[8], rw2[8];
    #pragma unroll
    for (int i = 0; i < 8; i++) {
        rb1[i] = __ldg(b1 + lane + 32 * i);
        rw2[i] = __ldg(W2 + lane + 32 * i);
    }

    int s, d;
    if (warp < E) { s = ei[warp];       d = ei[E + warp]; }
    else          { s = nei[warp - E];  d = nei[E + (warp - E)]; }
    s = clamp_idx(s);
    d = clamp_idx(d);

    const float* __restrict__ ar = g_A + (size_t)s * HID;
    const float* __restrict__ br = g_B + (size_t)d * HID;

    float acc = 0.f;
    #pragma unroll
    for (int i = 0; i < 8; i++) {
        int h = lane + 32 * i;
        float v = ar[h] + br[h] + rb1[i];
        acc = fmaf(fmaxf(v, 0.f), rw2[i], acc);
    }
    #pragma unroll
    for (int o = 16; o; o >>= 1)
        acc += __shfl_xor_sync(0xffffffffu, acc, o);

    if (lane == 0)
        out[warp] = acc + __ldg(b2);
}

// ---------------------------------------------------------------------------
extern "C" void kernel_launch(void* const* d_in, const int* in_sizes, int n_in,
                              void* d_out, int out_size)
{
    const float* x_src = (const float*)d_in[0];
    const float* x_dst = (const float*)d_in[1];
    const float* W1    = (const float*)d_in[2];   // [512, 256]
    const float* b1    = (const float*)d_in[3];
    const float* W2    = (const float*)d_in[4];   // [256, 1]
    const float* b2    = (const float*)d_in[5];
    const int*   ei    = (const int*)d_in[6];     // [2, E] int32 (jax x64 off)
    const int*   nei   = (const int*)d_in[7];
    float*       out   = (float*)d_out;

    const int M = in_sizes[0] / D;       // 100000
    const int E = in_sizes[6] / 2;       // 262144

    dim3 gblk(256);
    dim3 ggrd(HID / 128, (M + 127) / 128);
    // A = x_src @ W1[0:256,:]
    node_gemm_kernel<<<ggrd, gblk>>>(x_src, W1, M, 0);
    // B = x_dst @ W1[256:512,:]
    node_gemm_kernel<<<ggrd, gblk>>>(x_dst, W1 + (size_t)D * HID, M, 1);

    long long totalThreads = (long long)2 * E * 32;
    int threads = 256;
    int blocks  = (int)((totalThreads + threads - 1) / threads);
    edge_score_kernel<<<blocks, threads>>>(ei, nei, b1, W2, b2, out, E);
}

// round 3
// speedup vs baseline: 1.5186x; 1.5186x over previous
#include <cuda_runtime.h>
#include <cuda_bf16.h>
#include <cstdint>

#define NNODES 100000
#define D      256
#define HID    256

// Scratch (allocation-free rule -> device globals)
__device__ float g_A[(size_t)NNODES * HID];
__device__ float g_B[(size_t)NNODES * HID];
// Split + transposed weights: Wt[s][n][k], s=0 -> W1 rows 0..255 (src half),
// s=1 -> W1 rows 256..511 (dst half)
__device__ __nv_bfloat16 g_Wt_hi[2 * 256 * 256];
__device__ __nv_bfloat16 g_Wt_lo[2 * 256 * 256];

// ---------------------------------------------------------------------------
// W prep: split W1 (fp32 [512][256]) into bf16 hi/lo, transposed to [n][k].
// ---------------------------------------------------------------------------
__global__ void wprep_kernel(const float* __restrict__ W1)
{
    int idx = blockIdx.x * 256 + threadIdx.x;        // 0 .. 131071
    if (idx >= 2 * 256 * 256) return;
    int s = idx >> 16;
    int n = (idx >> 8) & 255;
    int k = idx & 255;
    float w = W1[(size_t)(s * 256 + k) * 256 + n];
    __nv_bfloat16 h = __float2bfloat16(w);
    float r = w - __bfloat162float(h);
    g_Wt_hi[idx] = h;
    g_Wt_lo[idx] = __float2bfloat16(r);
}

// ---------------------------------------------------------------------------
// Tensor-core GEMM, split-bf16 (3 segments: hi*Whi + hi*Wlo + lo*Whi).
// Out[M,256] = X[M,256] @ W[256,256] in ~fp32 accuracy.
// Block 128x128x32, 8 warps (4x2), warp tile 32x64, mma.m16n8k16.bf16.
// blockIdx.z: 0 -> (x_src, Wt[0], g_A), 1 -> (x_dst, Wt[1], g_B)
// ---------------------------------------------------------------------------
#define BM 128
#define BN 128
#define BK 32
#define LDT 40   // padded smem stride (bf16 elems)

__device__ __forceinline__ void mma16816(float* c, const uint32_t* a,
                                         uint32_t b0, uint32_t b1)
{
    asm volatile(
        "mma.sync.aligned.m16n8k16.row.col.f32.bf16.bf16.f32 "
        "{%0,%1,%2,%3}, {%4,%5,%6,%7}, {%8,%9}, {%0,%1,%2,%3};\n"
        : "+f"(c[0]), "+f"(c[1]), "+f"(c[2]), "+f"(c[3])
        : "r"(a[0]), "r"(a[1]), "r"(a[2]), "r"(a[3]), "r"(b0), "r"(b1));
}

__global__ __launch_bounds__(256, 2)
void mma_gemm_kernel(const float* __restrict__ Xsrc,
                     const float* __restrict__ Xdst,
                     int M)
{
    const int z = blockIdx.z;
    const float* __restrict__ X = z ? Xdst : Xsrc;
    float* __restrict__ Out = z ? g_B : g_A;
    const __nv_bfloat16* __restrict__ Whi = g_Wt_hi + (size_t)z * 256 * 256;
    const __nv_bfloat16* __restrict__ Wlo = g_Wt_lo + (size_t)z * 256 * 256;

    __shared__ __nv_bfloat16 sA[BM][LDT];
    __shared__ __nv_bfloat16 sB[BN][LDT];

    const int tid  = threadIdx.x;
    const int lane = tid & 31;
    const int wid  = tid >> 5;
    const int wm   = wid & 3;     // 0..3  (M direction, 32 rows each)
    const int wn   = wid >> 2;    // 0..1  (N direction, 64 cols each)
    const int g    = lane >> 2;   // 0..7
    const int tg   = lane & 3;    // 0..3

    const int bm = blockIdx.y * BM;
    const int bn = blockIdx.x * BN;

    float acc[2][8][4] = {};

    for (int seg = 0; seg < 3; seg++) {
        const __nv_bfloat16* __restrict__ Wp = (seg == 1) ? Wlo : Whi;
        const bool want_lo = (seg == 2);

        for (int k0 = 0; k0 < D; k0 += BK) {
            // ---- load X fp32 tile, convert to bf16 hi or lo, store to sA ----
            #pragma unroll
            for (int l = 0; l < 4; l++) {
                int f   = tid + l * 256;          // 0..1023 float4 slots
                int row = f >> 3;                  // 0..127
                int c4  = f & 7;                   // 0..7 (float4 within row)
                int gr  = bm + row;
                float4 v = make_float4(0.f, 0.f, 0.f, 0.f);
                if (gr < M)
                    v = *reinterpret_cast<const float4*>(X + (size_t)gr * D + k0 + c4 * 4);
                __nv_bfloat16 h0 = __float2bfloat16(v.x);
                __nv_bfloat16 h1 = __float2bfloat16(v.y);
                __nv_bfloat16 h2 = __float2bfloat16(v.z);
                __nv_bfloat16 h3 = __float2bfloat16(v.w);
                if (want_lo) {
                    h0 = __float2bfloat16(v.x - __bfloat162float(h0));
                    h1 = __float2bfloat16(v.y - __bfloat162float(h1));
                    h2 = __float2bfloat16(v.z - __bfloat162float(h2));
                    h3 = __float2bfloat16(v.w - __bfloat162float(h3));
                }
                __nv_bfloat162* p =
                    reinterpret_cast<__nv_bfloat162*>(&sA[row][c4 * 4]);
                p[0] = __nv_bfloat162(h0, h1);
                p[1] = __nv_bfloat162(h2, h3);
            }
            // ---- load W tile (transposed [n][k], bf16) to sB ----
            #pragma unroll
            for (int l = 0; l < 2; l++) {
                int f   = tid + l * 256;          // 0..511 (16B chunks)
                int row = f >> 2;                  // 0..127
                int ch  = f & 3;                   // 0..3
                uint4 w = *reinterpret_cast<const uint4*>(
                    Wp + (size_t)(bn + row) * 256 + k0 + ch * 8);
                *reinterpret_cast<uint4*>(&sB[row][ch * 8]) = w;
            }
            __syncthreads();

            // ---- 2 k-steps of m16n8k16 ----
            #pragma unroll
            for (int ks = 0; ks < 2; ks++) {
                const int kb = ks * 16;
                uint32_t af[2][4];
                #pragma unroll
                for (int i = 0; i < 2; i++) {
                    int r0 = wm * 32 + i * 16 + g;
                    af[i][0] = *reinterpret_cast<uint32_t*>(&sA[r0    ][kb + tg * 2    ]);
                    af[i][1] = *reinterpret_cast<uint32_t*>(&sA[r0 + 8][kb + tg * 2    ]);
                    af[i][2] = *reinterpret_cast<uint32_t*>(&sA[r0    ][kb + tg * 2 + 8]);
                    af[i][3] = *reinterpret_cast<uint32_t*>(&sA[r0 + 8][kb + tg * 2 + 8]);
                }
                #pragma unroll
                for (int j = 0; j < 8; j++) {
                    int nb = wn * 64 + j * 8 + g;
                    uint32_t b0 = *reinterpret_cast<uint32_t*>(&sB[nb][kb + tg * 2    ]);
                    uint32_t b1 = *reinterpret_cast<uint32_t*>(&sB[nb][kb + tg * 2 + 8]);
                    mma16816(acc[0][j], af[0], b0, b1);
                    mma16816(acc[1][j], af[1], b0, b1);
                }
            }
            __syncthreads();
        }
    }

    // ---- store C ----
    #pragma unroll
    for (int i = 0; i < 2; i++) {
        #pragma unroll
        for (int j = 0; j < 8; j++) {
            int r = bm + wm * 32 + i * 16 + g;
            int c = bn + wn * 64 + j * 8 + tg * 2;
            if (r < M)
                *reinterpret_cast<float2*>(Out + (size_t)r * HID + c) =
                    make_float2(acc[i][j][0], acc[i][j][1]);
            if (r + 8 < M)
                *reinterpret_cast<float2*>(Out + (size_t)(r + 8) * HID + c) =
                    make_float2(acc[i][j][2], acc[i][j][3]);
        }
    }
}

// ---------------------------------------------------------------------------
// Edge scoring: warp per edge slot (int32 indices).
// ---------------------------------------------------------------------------
__device__ __forceinline__ int clamp_idx(int v) {
    v = v < 0 ? 0 : v;
    return v >= NNODES ? NNODES - 1 : v;
}

__global__ __launch_bounds__(256)
void edge_score_kernel(const int* __restrict__ ei,
                       const int* __restrict__ nei,
                       const float* __restrict__ b1,
                       const float* __restrict__ W2,
                       const float* __restrict__ b2,
                       float* __restrict__ out,
                       int E)
{
    const int lane = threadIdx.x & 31;
    const int warp = (blockIdx.x * blockDim.x + threadIdx.x) >> 5;
    if (warp >= 2 * E) return;

    float rb1[8], rw2[8];
    #pragma unroll
    for (int i = 0; i < 8; i++) {
        rb1[i] = __ldg(b1 + lane + 32 * i);
        rw2[i] = __ldg(W2 + lane + 32 * i);
    }

    int s, d;
    if (warp < E) { s = ei[warp];       d = ei[E + warp]; }
    else          { s = nei[warp - E];  d = nei[E + (warp - E)]; }
    s = clamp_idx(s);
    d = clamp_idx(d);

    const float* __restrict__ ar = g_A + (size_t)s * HID;
    const float* __restrict__ br = g_B + (size_t)d * HID;

    float acc = 0.f;
    #pragma unroll
    for (int i = 0; i < 8; i++) {
        int h = lane + 32 * i;
        float v = ar[h] + br[h] + rb1[i];
        acc = fmaf(fmaxf(v, 0.f), rw2[i], acc);
    }
    #pragma unroll
    for (int o = 16; o; o >>= 1)
        acc += __shfl_xor_sync(0xffffffffu, acc, o);

    if (lane == 0)
        out[warp] = acc + __ldg(b2);
}

// ---------------------------------------------------------------------------
extern "C" void kernel_launch(void* const* d_in, const int* in_sizes, int n_in,
                              void* d_out, int out_size)
{
    const float* x_src = (const float*)d_in[0];
    const float* x_dst = (const float*)d_in[1];
    const float* W1    = (const float*)d_in[2];   // [512, 256]
    const float* b1    = (const float*)d_in[3];
    const float* W2    = (const float*)d_in[4];   // [256, 1]
    const float* b2    = (const float*)d_in[5];
    const int*   ei    = (const int*)d_in[6];     // [2, E] int32
    const int*   nei   = (const int*)d_in[7];
    float*       out   = (float*)d_out;

    const int M = in_sizes[0] / D;       // 100000
    const int E = in_sizes[6] / 2;       // 262144

    wprep_kernel<<<(2 * 256 * 256 + 255) / 256, 256>>>(W1);

    dim3 ggrd(HID / BN, (M + BM - 1) / BM, 2);
    mma_gemm_kernel<<<ggrd, 256>>>(x_src, x_dst, M);

    long long totalThreads = (long long)2 * E * 32;
    int threads = 256;
    int blocks  = (int)((totalThreads + threads - 1) / threads);
    edge_score_kernel<<<blocks, threads>>>(ei, nei, b1, W2, b2, out, E);
}

// round 5
// speedup vs baseline: 1.9514x; 1.2850x over previous
#include <cuda_runtime.h>
#include <cuda_fp16.h>
#include <cuda_bf16.h>
#include <cstdint>

#define NNODES 100000
#define D      256
#define HID    256

// ---------------- device scratch (allocation-free rule) ----------------
__device__ __half g_A[(size_t)NNODES * HID];
__device__ __half g_B[(size_t)NNODES * HID];
// Split + transposed weights: Wt[z][n][k] bf16, z=0 src half, z=1 dst half
__device__ __nv_bfloat16 g_Wt_hi[2 * 256 * 256];
__device__ __nv_bfloat16 g_Wt_lo[2 * 256 * 256];

// ---------------- helpers ----------------
__device__ __forceinline__ uint32_t smem_u32(const void* p) {
    uint32_t a;
    asm("{ .reg .u64 t; cvta.to.shared.u64 t, %1; cvt.u32.u64 %0, t; }"
        : "=r"(a) : "l"(p));
    return a;
}
__device__ __forceinline__ void ldsm4(uint32_t* r, uint32_t addr) {
    asm volatile("ldmatrix.sync.aligned.m8n8.x4.shared.b16 {%0,%1,%2,%3}, [%4];"
                 : "=r"(r[0]), "=r"(r[1]), "=r"(r[2]), "=r"(r[3]) : "r"(addr));
}
__device__ __forceinline__ void mma16816(float* c, const uint32_t* a,
                                         uint32_t b0, uint32_t b1)
{
    asm volatile(
        "mma.sync.aligned.m16n8k16.row.col.f32.bf16.bf16.f32 "
        "{%0,%1,%2,%3}, {%4,%5,%6,%7}, {%8,%9}, {%0,%1,%2,%3};\n"
        : "+f"(c[0]), "+f"(c[1]), "+f"(c[2]), "+f"(c[3])
        : "r"(a[0]), "r"(a[1]), "r"(a[2]), "r"(a[3]), "r"(b0), "r"(b1));
}
__device__ __forceinline__ void cp16(uint32_t dst, const void* src) {
    asm volatile("cp.async.cg.shared.global [%0], [%1], 16;"
                 :: "r"(dst), "l"(src));
}
#define CP_COMMIT() asm volatile("cp.async.commit_group;")
#define CP_WAIT0()  asm volatile("cp.async.wait_group 0;")

// ---------------- smem layout (bytes) ----------------
// row stride 80B (32 bf16 + 8 pad) -> ldmatrix conflict-free (banks 20r mod 32)
#define LDTB    80
#define OFF_AHI 0
#define OFF_ALO 10240
#define OFF_BHI 20480
#define OFF_BLO 30720
#define BUFB    40960
#define SMEMB   (2 * BUFB)

// ---------------------------------------------------------------------------
// W prep: split W1 (fp32 [512][256]) into bf16 hi/lo, transposed to [z][n][k].
// ---------------------------------------------------------------------------
__global__ void wprep_kernel(const float* __restrict__ W1)
{
    int idx = blockIdx.x * 256 + threadIdx.x;    // 0 .. 131071
    if (idx >= 2 * 256 * 256) return;
    int z = idx >> 16;
    int n = (idx >> 8) & 255;
    int k = idx & 255;
    float w = W1[(size_t)(z * 256 + k) * 256 + n];
    __nv_bfloat16 h = __float2bfloat16(w);
    g_Wt_hi[idx] = h;
    g_Wt_lo[idx] = __float2bfloat16(w - __bfloat162float(h));
}

// ---------------------------------------------------------------------------
// Split-bf16 GEMM, single K pass, 3 MMA terms per fragment set.
// Out[M,256](fp16) = X[M,256] @ W[256,256]
// Block 128x128, BK=32, 512 threads (16 warps, 4x4), warp tile 32x32.
// blockIdx.z: 0 -> (x_src, Wt[0], g_A), 1 -> (x_dst, Wt[1], g_B)
// ---------------------------------------------------------------------------
__global__ __launch_bounds__(512, 1)
void mma_gemm_kernel(const float* __restrict__ Xsrc,
                     const float* __restrict__ Xdst, int M)
{
    extern __shared__ char smem[];
    const uint32_t sb = smem_u32(smem);

    const int z = blockIdx.z;
    const float* __restrict__ X = z ? Xdst : Xsrc;
    __half* __restrict__ Out = z ? g_B : g_A;
    const __nv_bfloat16* __restrict__ Whi = g_Wt_hi + (size_t)z * 65536;
    const __nv_bfloat16* __restrict__ Wlo = g_Wt_lo + (size_t)z * 65536;

    const int tid  = threadIdx.x;
    const int lane = tid & 31;
    const int wid  = tid >> 5;
    const int wm   = wid & 3;      // 0..3 (M dir, 32 rows)
    const int wn   = wid >> 2;     // 0..3 (N dir, 32 cols)
    const int bm   = blockIdx.y * 128;
    const int bn   = blockIdx.x * 128;

    // A global-load slots: 2 float4 per thread per chunk
    const int arow[2] = { (tid + 0)   >> 3, (tid + 512) >> 3 };
    const int ac4 [2] = { (tid + 0)   & 7,  (tid + 512) & 7  };
    // B cp.async slot: 1 x 16B per thread per (hi,lo)
    const int brow = tid >> 2;
    const int bch  = tid & 3;

    float acc[2][4][4] = {};
    float4 pref[2];

    auto load_A = [&](int c) {
        #pragma unroll
        for (int l = 0; l < 2; l++) {
            int gr = bm + arow[l];
            pref[l] = make_float4(0.f, 0.f, 0.f, 0.f);
            if (gr < M)
                pref[l] = *reinterpret_cast<const float4*>(
                    X + (size_t)gr * D + c * 32 + ac4[l] * 4);
        }
    };
    auto store_A = [&](int buf) {
        #pragma unroll
        for (int l = 0; l < 2; l++) {
            float f[4] = {pref[l].x, pref[l].y, pref[l].z, pref[l].w};
            union { uint2 u; __nv_bfloat162 h2[2]; } uh, ul;
            #pragma unroll
            for (int j = 0; j < 2; j++) {
                __nv_bfloat16 h0 = __float2bfloat16(f[2*j]);
                __nv_bfloat16 h1 = __float2bfloat16(f[2*j+1]);
                uh.h2[j] = __nv_bfloat162(h0, h1);
                ul.h2[j] = __nv_bfloat162(
                    __float2bfloat16(f[2*j]   - __bfloat162float(h0)),
                    __float2bfloat16(f[2*j+1] - __bfloat162float(h1)));
            }
            char* base = smem + buf * BUFB + arow[l] * LDTB + ac4[l] * 8;
            *reinterpret_cast<uint2*>(base + OFF_AHI) = uh.u;
            *reinterpret_cast<uint2*>(base + OFF_ALO) = ul.u;
        }
    };
    auto copy_B = [&](int c, int buf) {
        uint32_t dst = sb + buf * BUFB + brow * LDTB + bch * 16;
        size_t   so  = (size_t)(bn + brow) * 256 + c * 32 + bch * 8;
        cp16(dst + OFF_BHI, Whi + so);
        cp16(dst + OFF_BLO, Wlo + so);
        CP_COMMIT();
    };

    // ---- prologue: chunk 0 -> buf 0 ----
    load_A(0);
    store_A(0);
    copy_B(0, 0);
    CP_WAIT0();
    __syncthreads();

    const int lrow = lane & 15;
    const int lcol = (lane >> 4) * 8;   // bf16 elems

    for (int c = 0; c < 8; c++) {
        const int buf = c & 1;
        if (c < 7) {
            load_A(c + 1);
            copy_B(c + 1, buf ^ 1);
        }

        const uint32_t b0 = sb + buf * BUFB;
        #pragma unroll
        for (int ks = 0; ks < 2; ks++) {
            const int kb = ks * 16;
            uint32_t ahi[2][4], alo[2][4], bhi[2][4], blo[2][4];
            const uint32_t coff = (kb + lcol) * 2;
            #pragma unroll
            for (int i = 0; i < 2; i++) {
                uint32_t ar = (uint32_t)(wm * 32 + i * 16 + lrow) * LDTB + coff;
                ldsm4(ahi[i], b0 + OFF_AHI + ar);
                ldsm4(alo[i], b0 + OFF_ALO + ar);
            }
            #pragma unroll
            for (int jj = 0; jj < 2; jj++) {
                uint32_t br = (uint32_t)(wn * 32 + jj * 16 + lrow) * LDTB + coff;
                ldsm4(bhi[jj], b0 + OFF_BHI + br);
                ldsm4(blo[jj], b0 + OFF_BLO + br);
            }
            #pragma unroll
            for (int i = 0; i < 2; i++)
                #pragma unroll
                for (int j = 0; j < 4; j++) {
                    const int jj = j >> 1, s = j & 1;
                    mma16816(acc[i][j], ahi[i], bhi[jj][s], bhi[jj][s + 2]);
                    mma16816(acc[i][j], ahi[i], blo[jj][s], blo[jj][s + 2]);
                    mma16816(acc[i][j], alo[i], bhi[jj][s], bhi[jj][s + 2]);
                }
        }

        if (c < 7) {
            store_A(buf ^ 1);
            CP_WAIT0();
        }
        __syncthreads();
    }

    // ---- epilogue: fp32 acc -> fp16 store ----
    const int g  = lane >> 2;
    const int tg = lane & 3;
    #pragma unroll
    for (int i = 0; i < 2; i++)
        #pragma unroll
        for (int j = 0; j < 4; j++) {
            int r0 = bm + wm * 32 + i * 16 + g;
            int cc = bn + wn * 32 + j * 8 + tg * 2;
            if (r0 < M)
                *reinterpret_cast<__half2*>(Out + (size_t)r0 * HID + cc) =
                    __floats2half2_rn(acc[i][j][0], acc[i][j][1]);
            if (r0 + 8 < M)
                *reinterpret_cast<__half2*>(Out + (size_t)(r0 + 8) * HID + cc) =
                    __floats2half2_rn(acc[i][j][2], acc[i][j][3]);
        }
}

// ---------------------------------------------------------------------------
// Edge scoring: warp per edge slot (int32 indices), fp16 activations.
// Lane handles h = lane*8 .. lane*8+7 -> one uint4 (16B) per row per lane.
// ---------------------------------------------------------------------------
__device__ __forceinline__ int clamp_idx(int v) {
    v = v < 0 ? 0 : v;
    return v >= NNODES ? NNODES - 1 : v;
}

__global__ __launch_bounds__(256)
void edge_score_kernel(const int* __restrict__ ei,
                       const int* __restrict__ nei,
                       const float* __restrict__ b1,
                       const float* __restrict__ W2,
                       const float* __restrict__ b2,
                       float* __restrict__ out,
                       int E)
{
    const int lane = threadIdx.x & 31;
    const int warp = (blockIdx.x * blockDim.x + threadIdx.x) >> 5;
    if (warp >= 2 * E) return;

    float4 rb1a = *reinterpret_cast<const float4*>(b1 + lane * 8);
    float4 rb1b = *reinterpret_cast<const float4*>(b1 + lane * 8 + 4);
    float4 rw2a = *reinterpret_cast<const float4*>(W2 + lane * 8);
    float4 rw2b = *reinterpret_cast<const float4*>(W2 + lane * 8 + 4);
    float rb1[8] = {rb1a.x, rb1a.y, rb1a.z, rb1a.w, rb1b.x, rb1b.y, rb1b.z, rb1b.w};
    float rw2[8] = {rw2a.x, rw2a.y, rw2a.z, rw2a.w, rw2b.x, rw2b.y, rw2b.z, rw2b.w};

    int s, d;
    if (warp < E) { s = ei[warp];       d = ei[E + warp]; }
    else          { s = nei[warp - E];  d = nei[E + (warp - E)]; }
    s = clamp_idx(s);
    d = clamp_idx(d);

    uint4 au = *reinterpret_cast<const uint4*>(g_A + (size_t)s * HID + lane * 8);
    uint4 bu = *reinterpret_cast<const uint4*>(g_B + (size_t)d * HID + lane * 8);
    const __half2* ah = reinterpret_cast<const __half2*>(&au);
    const __half2* bh = reinterpret_cast<const __half2*>(&bu);

    float acc = 0.f;
    #pragma unroll
    for (int q = 0; q < 4; q++) {
        float2 af = __half22float2(ah[q]);
        float2 bf = __half22float2(bh[q]);
        float v0 = af.x + bf.x + rb1[2*q];
        float v1 = af.y + bf.y + rb1[2*q+1];
        acc = fmaf(fmaxf(v0, 0.f), rw2[2*q],   acc);
        acc = fmaf(fmaxf(v1, 0.f), rw2[2*q+1], acc);
    }
    #pragma unroll
    for (int o = 16; o; o >>= 1)
        acc += __shfl_xor_sync(0xffffffffu, acc, o);

    if (lane == 0)
        out[warp] = acc + __ldg(b2);
}

// ---------------------------------------------------------------------------
extern "C" void kernel_launch(void* const* d_in, const int* in_sizes, int n_in,
                              void* d_out, int out_size)
{
    const float* x_src = (const float*)d_in[0];
    const float* x_dst = (const float*)d_in[1];
    const float* W1    = (const float*)d_in[2];   // [512, 256]
    const float* b1    = (const float*)d_in[3];
    const float* W2    = (const float*)d_in[4];   // [256, 1]
    const float* b2    = (const float*)d_in[5];
    const int*   ei    = (const int*)d_in[6];     // [2, E] int32
    const int*   nei   = (const int*)d_in[7];
    float*       out   = (float*)d_out;

    const int M = in_sizes[0] / D;       // 100000
    const int E = in_sizes[6] / 2;       // 262144

    cudaFuncSetAttribute(mma_gemm_kernel,
                         cudaFuncAttributeMaxDynamicSharedMemorySize, SMEMB);

    wprep_kernel<<<(2 * 256 * 256 + 255) / 256, 256>>>(W1);

    dim3 ggrd(HID / 128, (M + 127) / 128, 2);
    mma_gemm_kernel<<<ggrd, 512, SMEMB>>>(x_src, x_dst, M);

    long long totalThreads = (long long)2 * E * 32;
    int threads = 256;
    int blocks  = (int)((totalThreads + threads - 1) / threads);
    edge_score_kernel<<<blocks, threads>>>(ei, nei, b1, W2, b2, out, E);
}

// round 6
// speedup vs baseline: 3.1157x; 1.5967x over previous
#include <cuda_runtime.h>
#include <cuda_fp16.h>
#include <cstdint>

#define NNODES 100000
#define D      256
#define HID    256

// ---------------- device scratch (allocation-free rule) ----------------
__device__ __half g_A[(size_t)NNODES * HID];
__device__ __half g_B[(size_t)NNODES * HID];
// Transposed fp16 weights: Wt[z][n][k], z=0 src half, z=1 dst half
__device__ __half g_Wt[2 * 256 * 256];

// ---------------- helpers ----------------
__device__ __forceinline__ uint32_t smem_u32(const void* p) {
    uint32_t a;
    asm("{ .reg .u64 t; cvta.to.shared.u64 t, %1; cvt.u32.u64 %0, t; }"
        : "=r"(a) : "l"(p));
    return a;
}
__device__ __forceinline__ void ldsm4(uint32_t* r, uint32_t addr) {
    asm volatile("ldmatrix.sync.aligned.m8n8.x4.shared.b16 {%0,%1,%2,%3}, [%4];"
                 : "=r"(r[0]), "=r"(r[1]), "=r"(r[2]), "=r"(r[3]) : "r"(addr));
}
__device__ __forceinline__ void mma16816(float* c, const uint32_t* a,
                                         uint32_t b0, uint32_t b1)
{
    asm volatile(
        "mma.sync.aligned.m16n8k16.row.col.f32.f16.f16.f32 "
        "{%0,%1,%2,%3}, {%4,%5,%6,%7}, {%8,%9}, {%0,%1,%2,%3};\n"
        : "+f"(c[0]), "+f"(c[1]), "+f"(c[2]), "+f"(c[3])
        : "r"(a[0]), "r"(a[1]), "r"(a[2]), "r"(a[3]), "r"(b0), "r"(b1));
}
__device__ __forceinline__ void cp16(uint32_t dst, const void* src) {
    asm volatile("cp.async.cg.shared.global [%0], [%1], 16;"
                 :: "r"(dst), "l"(src));
}
#define CP_COMMIT() asm volatile("cp.async.commit_group;")
#define CP_WAIT0()  asm volatile("cp.async.wait_group 0;")

// ---------------- smem layout (bytes) ----------------
// BK=32 -> 64B data/row + 16B pad = 80B stride (ldmatrix conflict-free)
#define LDTB   80
#define OFF_A  0
#define OFF_B  10240
#define BUFB   20480
#define SMEMB  (2 * BUFB)

// ---------------------------------------------------------------------------
// W prep: W1 fp32 [512][256] -> fp16, transposed to [z][n][k].
// ---------------------------------------------------------------------------
__global__ void wprep_kernel(const float* __restrict__ W1)
{
    int idx = blockIdx.x * 256 + threadIdx.x;    // 0 .. 131071
    if (idx >= 2 * 256 * 256) return;
    int z = idx >> 16;
    int n = (idx >> 8) & 255;
    int k = idx & 255;
    g_Wt[idx] = __float2half_rn(W1[(size_t)(z * 256 + k) * 256 + n]);
}

// ---------------------------------------------------------------------------
// fp16 GEMM with fp32 accumulate: Out[M,256](fp16) = X[M,256] @ W[256,256].
// Block 128x128, BK=32, 256 threads (8 warps 4x2), warp tile 32x64.
// blockIdx.z: 0 -> (x_src, Wt[0], g_A), 1 -> (x_dst, Wt[1], g_B)
// ---------------------------------------------------------------------------
__global__ __launch_bounds__(256, 2)
void mma_gemm_kernel(const float* __restrict__ Xsrc,
                     const float* __restrict__ Xdst, int M)
{
    extern __shared__ char smem[];
    const uint32_t sb = smem_u32(smem);

    const int z = blockIdx.z;
    const float* __restrict__ X = z ? Xdst : Xsrc;
    __half* __restrict__ Out = z ? g_B : g_A;
    const __half* __restrict__ Wt = g_Wt + (size_t)z * 65536;

    const int tid  = threadIdx.x;
    const int lane = tid & 31;
    const int wid  = tid >> 5;
    const int wm   = wid & 3;      // 0..3 (M dir, 32 rows)
    const int wn   = wid >> 2;     // 0..1 (N dir, 64 cols)
    const int bm   = blockIdx.y * 128;
    const int bn   = blockIdx.x * 128;

    // A global-load slots: 4 float4 per thread per chunk (128 rows x 32 fp32)
    int arow[4], ac4[4];
    #pragma unroll
    for (int l = 0; l < 4; l++) {
        int f = tid + l * 256;
        arow[l] = f >> 3;          // 0..127
        ac4[l]  = f & 7;           // 0..7
    }
    // B cp.async slots: 2 x 16B per thread per chunk (128 rows x 32 fp16)
    const int brow0 = tid >> 2,        bch0 = tid & 3;
    const int brow1 = (tid + 256) >> 2, bch1 = (tid + 256) & 3;

    float acc[2][8][4] = {};
    float4 pref[4];

    auto load_A = [&](int c) {
        #pragma unroll
        for (int l = 0; l < 4; l++) {
            int gr = bm + arow[l];
            pref[l] = make_float4(0.f, 0.f, 0.f, 0.f);
            if (gr < M)
                pref[l] = *reinterpret_cast<const float4*>(
                    X + (size_t)gr * D + c * 32 + ac4[l] * 4);
        }
    };
    auto store_A = [&](int buf) {
        #pragma unroll
        for (int l = 0; l < 4; l++) {
            __half2 h0 = __floats2half2_rn(pref[l].x, pref[l].y);
            __half2 h1 = __floats2half2_rn(pref[l].z, pref[l].w);
            char* p = smem + buf * BUFB + OFF_A + arow[l] * LDTB + ac4[l] * 8;
            *reinterpret_cast<__half2*>(p)     = h0;
            *reinterpret_cast<__half2*>(p + 4) = h1;
        }
    };
    auto copy_B = [&](int c, int buf) {
        uint32_t base = sb + buf * BUFB + OFF_B;
        cp16(base + brow0 * LDTB + bch0 * 16,
             Wt + (size_t)(bn + brow0) * 256 + c * 32 + bch0 * 8);
        cp16(base + brow1 * LDTB + bch1 * 16,
             Wt + (size_t)(bn + brow1) * 256 + c * 32 + bch1 * 8);
        CP_COMMIT();
    };

    // ---- prologue: chunk 0 -> buf 0 ----
    load_A(0);
    store_A(0);
    copy_B(0, 0);
    CP_WAIT0();
    __syncthreads();

    const int lrow = lane & 15;
    const int lcol = (lane >> 4) * 8;   // halves

    for (int c = 0; c < 8; c++) {
        const int buf = c & 1;
        if (c < 7) {
            load_A(c + 1);
            copy_B(c + 1, buf ^ 1);
        }

        const uint32_t b0 = sb + buf * BUFB;
        #pragma unroll
        for (int ks = 0; ks < 2; ks++) {
            const int kb = ks * 16;
            const uint32_t coff = (kb + lcol) * 2;
            uint32_t af[2][4], bf[4][4];
            #pragma unroll
            for (int i = 0; i < 2; i++)
                ldsm4(af[i], b0 + OFF_A +
                      (uint32_t)(wm * 32 + i * 16 + lrow) * LDTB + coff);
            #pragma unroll
            for (int jj = 0; jj < 4; jj++)
                ldsm4(bf[jj], b0 + OFF_B +
                      (uint32_t)(wn * 64 + jj * 16 + lrow) * LDTB + coff);
            #pragma unroll
            for (int i = 0; i < 2; i++)
                #pragma unroll
                for (int j = 0; j < 8; j++) {
                    const int jj = j >> 1, s = j & 1;
                    mma16816(acc[i][j], af[i], bf[jj][s], bf[jj][s + 2]);
                }
        }

        if (c < 7) {
            store_A(buf ^ 1);
            CP_WAIT0();
        }
        __syncthreads();
    }

    // ---- epilogue: fp32 acc -> fp16 store ----
    const int g  = lane >> 2;
    const int tg = lane & 3;
    #pragma unroll
    for (int i = 0; i < 2; i++)
        #pragma unroll
        for (int j = 0; j < 8; j++) {
            int r0 = bm + wm * 32 + i * 16 + g;
            int cc = bn + wn * 64 + j * 8 + tg * 2;
            if (r0 < M)
                *reinterpret_cast<__half2*>(Out + (size_t)r0 * HID + cc) =
                    __floats2half2_rn(acc[i][j][0], acc[i][j][1]);
            if (r0 + 8 < M)
                *reinterpret_cast<__half2*>(Out + (size_t)(r0 + 8) * HID + cc) =
                    __floats2half2_rn(acc[i][j][2], acc[i][j][3]);
        }
}

// ---------------------------------------------------------------------------
// Edge scoring: warp per edge slot (int32 indices), fp16 activations.
// ---------------------------------------------------------------------------
__device__ __forceinline__ int clamp_idx(int v) {
    v = v < 0 ? 0 : v;
    return v >= NNODES ? NNODES - 1 : v;
}

__global__ __launch_bounds__(256)
void edge_score_kernel(const int* __restrict__ ei,
                       const int* __restrict__ nei,
                       const float* __restrict__ b1,
                       const float* __restrict__ W2,
                       const float* __restrict__ b2,
                       float* __restrict__ out,
                       int E)
{
    const int lane = threadIdx.x & 31;
    const int warp = (blockIdx.x * blockDim.x + threadIdx.x) >> 5;
    if (warp >= 2 * E) return;

    float4 rb1a = *reinterpret_cast<const float4*>(b1 + lane * 8);
    float4 rb1b = *reinterpret_cast<const float4*>(b1 + lane * 8 + 4);
    float4 rw2a = *reinterpret_cast<const float4*>(W2 + lane * 8);
    float4 rw2b = *reinterpret_cast<const float4*>(W2 + lane * 8 + 4);
    float rb1[8] = {rb1a.x, rb1a.y, rb1a.z, rb1a.w, rb1b.x, rb1b.y, rb1b.z, rb1b.w};
    float rw2[8] = {rw2a.x, rw2a.y, rw2a.z, rw2a.w, rw2b.x, rw2b.y, rw2b.z, rw2b.w};

    int s, d;
    if (warp < E) { s = ei[warp];       d = ei[E + warp]; }
    else          { s = nei[warp - E];  d = nei[E + (warp - E)]; }
    s = clamp_idx(s);
    d = clamp_idx(d);

    uint4 au = *reinterpret_cast<const uint4*>(g_A + (size_t)s * HID + lane * 8);
    uint4 bu = *reinterpret_cast<const uint4*>(g_B + (size_t)d * HID + lane * 8);
    const __half2* ah = reinterpret_cast<const __half2*>(&au);
    const __half2* bh = reinterpret_cast<const __half2*>(&bu);

    float acc = 0.f;
    #pragma unroll
    for (int q = 0; q < 4; q++) {
        float2 af = __half22float2(ah[q]);
        float2 bf = __half22float2(bh[q]);
        float v0 = af.x + bf.x + rb1[2*q];
        float v1 = af.y + bf.y + rb1[2*q+1];
        acc = fmaf(fmaxf(v0, 0.f), rw2[2*q],   acc);
        acc = fmaf(fmaxf(v1, 0.f), rw2[2*q+1], acc);
    }
    #pragma unroll
    for (int o = 16; o; o >>= 1)
        acc += __shfl_xor_sync(0xffffffffu, acc, o);

    if (lane == 0)
        out[warp] = acc + __ldg(b2);
}

// ---------------------------------------------------------------------------
extern "C" void kernel_launch(void* const* d_in, const int* in_sizes, int n_in,
                              void* d_out, int out_size)
{
    const float* x_src = (const float*)d_in[0];
    const float* x_dst = (const float*)d_in[1];
    const float* W1    = (const float*)d_in[2];   // [512, 256]
    const float* b1    = (const float*)d_in[3];
    const float* W2    = (const float*)d_in[4];   // [256, 1]
    const float* b2    = (const float*)d_in[5];
    const int*   ei    = (const int*)d_in[6];     // [2, E] int32
    const int*   nei   = (const int*)d_in[7];
    float*       out   = (float*)d_out;

    const int M = in_sizes[0] / D;       // 100000
    const int E = in_sizes[6] / 2;       // 262144

    cudaFuncSetAttribute(mma_gemm_kernel,
                         cudaFuncAttributeMaxDynamicSharedMemorySize, SMEMB);

    wprep_kernel<<<(2 * 256 * 256 + 255) / 256, 256>>>(W1);

    dim3 ggrd(HID / 128, (M + 127) / 128, 2);
    mma_gemm_kernel<<<ggrd, 256, SMEMB>>>(x_src, x_dst, M);

    long long totalThreads = (long long)2 * E * 32;
    int threads = 256;
    int blocks  = (int)((totalThreads + threads - 1) / threads);
    edge_score_kernel<<<blocks, threads>>>(ei, nei, b1, W2, b2, out, E);
}

// round 7
// speedup vs baseline: 3.5110x; 1.1269x over previous
#include <cuda_runtime.h>
#include <cuda_fp16.h>
#include <cstdint>

#define NNODES 100000
#define D      256
#define HID    256

// ---------------- device scratch (allocation-free rule) ----------------
__device__ __half g_A[(size_t)NNODES * HID];   // xs@W1top + b1  (fp16)
__device__ __half g_B[(size_t)NNODES * HID];   // xd@W1bot       (fp16)
// Transposed fp16 weights: Wt[z][n][k], z=0 src half, z=1 dst half
__device__ __half g_Wt[2 * 256 * 256];

// ---------------- helpers ----------------
__device__ __forceinline__ uint32_t smem_u32(const void* p) {
    uint32_t a;
    asm("{ .reg .u64 t; cvta.to.shared.u64 t, %1; cvt.u32.u64 %0, t; }"
        : "=r"(a) : "l"(p));
    return a;
}
__device__ __forceinline__ void ldsm4(uint32_t* r, uint32_t addr) {
    asm volatile("ldmatrix.sync.aligned.m8n8.x4.shared.b16 {%0,%1,%2,%3}, [%4];"
                 : "=r"(r[0]), "=r"(r[1]), "=r"(r[2]), "=r"(r[3]) : "r"(addr));
}
__device__ __forceinline__ void mma16816(float* c, const uint32_t* a,
                                         uint32_t b0, uint32_t b1)
{
    asm volatile(
        "mma.sync.aligned.m16n8k16.row.col.f32.f16.f16.f32 "
        "{%0,%1,%2,%3}, {%4,%5,%6,%7}, {%8,%9}, {%0,%1,%2,%3};\n"
        : "+f"(c[0]), "+f"(c[1]), "+f"(c[2]), "+f"(c[3])
        : "r"(a[0]), "r"(a[1]), "r"(a[2]), "r"(a[3]), "r"(b0), "r"(b1));
}
__device__ __forceinline__ void cp16(uint32_t dst, const void* src) {
    asm volatile("cp.async.cg.shared.global [%0], [%1], 16;"
                 :: "r"(dst), "l"(src));
}
#define CP_COMMIT() asm volatile("cp.async.commit_group;")
#define CP_WAIT0()  asm volatile("cp.async.wait_group 0;")

// streaming fp32x4 load (read-once data: keep out of L2 as much as possible)
__device__ __forceinline__ float4 ldcs4(const float* p) {
    float4 v;
    asm volatile("ld.global.cs.v4.f32 {%0,%1,%2,%3}, [%4];"
                 : "=f"(v.x), "=f"(v.y), "=f"(v.z), "=f"(v.w) : "l"(p));
    return v;
}

// ---------------- smem layout (bytes) ----------------
// BK=32 -> 64B data/row + 16B pad = 80B stride (ldmatrix conflict-free)
#define LDTB   80
#define OFF_A  0
#define OFF_B  10240
#define BUFB   20480
#define SMEMB  (2 * BUFB)

// ---------------------------------------------------------------------------
// W prep: W1 fp32 [512][256] -> fp16, transposed to [z][n][k].
// ---------------------------------------------------------------------------
__global__ void wprep_kernel(const float* __restrict__ W1)
{
    int idx = blockIdx.x * 256 + threadIdx.x;    // 0 .. 131071
    if (idx >= 2 * 256 * 256) return;
    int z = idx >> 16;
    int n = (idx >> 8) & 255;
    int k = idx & 255;
    g_Wt[idx] = __float2half_rn(W1[(size_t)(z * 256 + k) * 256 + n]);
}

// ---------------------------------------------------------------------------
// fp16 GEMM with fp32 accumulate: Out[M,256](fp16) = X[M,256] @ W[256,256]
// (+ b1 folded into the z=0 output).
// Block 128x128, BK=32, 256 threads (8 warps 4x2), warp tile 32x64.
// z passed as parameter: 0 -> (x_src, Wt[0], g_A, +b1), 1 -> (x_dst, Wt[1], g_B)
// ---------------------------------------------------------------------------
__global__ __launch_bounds__(256, 2)
void mma_gemm_kernel(const float* __restrict__ X,
                     const float* __restrict__ b1,
                     int M, int z)
{
    extern __shared__ char smem[];
    const uint32_t sb = smem_u32(smem);

    __half* __restrict__ Out = z ? g_B : g_A;
    const __half* __restrict__ Wt = g_Wt + (size_t)z * 65536;

    const int tid  = threadIdx.x;
    const int lane = tid & 31;
    const int wid  = tid >> 5;
    const int wm   = wid & 3;      // 0..3 (M dir, 32 rows)
    const int wn   = wid >> 2;     // 0..1 (N dir, 64 cols)
    const int bm   = blockIdx.y * 128;
    const int bn   = blockIdx.x * 128;
    const bool full = (bm + 128 <= M);

    // A global-load slots: 4 float4 per thread per chunk (128 rows x 32 fp32)
    int arow[4], ac4[4];
    #pragma unroll
    for (int l = 0; l < 4; l++) {
        int f = tid + l * 256;
        arow[l] = f >> 3;          // 0..127
        ac4[l]  = f & 7;           // 0..7
    }
    // B cp.async slots: 2 x 16B per thread per chunk (128 rows x 32 fp16)
    const int brow0 = tid >> 2,         bch0 = tid & 3;
    const int brow1 = (tid + 256) >> 2, bch1 = (tid + 256) & 3;

    float acc[2][8][4] = {};
    float4 pref[4];

    auto load_A = [&](int c) {
        if (full) {
            #pragma unroll
            for (int l = 0; l < 4; l++)
                pref[l] = ldcs4(X + (size_t)(bm + arow[l]) * D + c * 32 + ac4[l] * 4);
        } else {
            #pragma unroll
            for (int l = 0; l < 4; l++) {
                int gr = bm + arow[l];
                pref[l] = make_float4(0.f, 0.f, 0.f, 0.f);
                if (gr < M)
                    pref[l] = ldcs4(X + (size_t)gr * D + c * 32 + ac4[l] * 4);
            }
        }
    };
    auto store_A = [&](int buf) {
        #pragma unroll
        for (int l = 0; l < 4; l++) {
            __half2 h0 = __floats2half2_rn(pref[l].x, pref[l].y);
            __half2 h1 = __floats2half2_rn(pref[l].z, pref[l].w);
            char* p = smem + buf * BUFB + OFF_A + arow[l] * LDTB + ac4[l] * 8;
            *reinterpret_cast<__half2*>(p)     = h0;
            *reinterpret_cast<__half2*>(p + 4) = h1;
        }
    };
    auto copy_B = [&](int c, int buf) {
        uint32_t base = sb + buf * BUFB + OFF_B;
        cp16(base + brow0 * LDTB + bch0 * 16,
             Wt + (size_t)(bn + brow0) * 256 + c * 32 + bch0 * 8);
        cp16(base + brow1 * LDTB + bch1 * 16,
             Wt + (size_t)(bn + brow1) * 256 + c * 32 + bch1 * 8);
        CP_COMMIT();
    };

    // ---- prologue: chunk 0 -> buf 0 ----
    load_A(0);
    store_A(0);
    copy_B(0, 0);
    CP_WAIT0();
    __syncthreads();

    const int lrow = lane & 15;
    const int lcol = (lane >> 4) * 8;   // halves

    for (int c = 0; c < 8; c++) {
        const int buf = c & 1;
        if (c < 7) {
            load_A(c + 1);
            copy_B(c + 1, buf ^ 1);
        }

        const uint32_t b0 = sb + buf * BUFB;
        #pragma unroll
        for (int ks = 0; ks < 2; ks++) {
            const int kb = ks * 16;
            const uint32_t coff = (kb + lcol) * 2;
            uint32_t af[2][4], bf[4][4];
            #pragma unroll
            for (int i = 0; i < 2; i++)
                ldsm4(af[i], b0 + OFF_A +
                      (uint32_t)(wm * 32 + i * 16 + lrow) * LDTB + coff);
            #pragma unroll
            for (int jj = 0; jj < 4; jj++)
                ldsm4(bf[jj], b0 + OFF_B +
                      (uint32_t)(wn * 64 + jj * 16 + lrow) * LDTB + coff);
            #pragma unroll
            for (int i = 0; i < 2; i++)
                #pragma unroll
                for (int j = 0; j < 8; j++) {
                    const int jj = j >> 1, s = j & 1;
                    mma16816(acc[i][j], af[i], bf[jj][s], bf[jj][s + 2]);
                }
        }

        if (c < 7) {
            store_A(buf ^ 1);
            CP_WAIT0();
        }
        __syncthreads();
    }

    // ---- epilogue: fp32 acc (+b1 for z=0) -> fp16 store ----
    const int g  = lane >> 2;
    const int tg = lane & 3;
    #pragma unroll
    for (int i = 0; i < 2; i++)
        #pragma unroll
        for (int j = 0; j < 8; j++) {
            int r0 = bm + wm * 32 + i * 16 + g;
            int cc = bn + wn * 64 + j * 8 + tg * 2;
            float bias0 = 0.f, bias1 = 0.f;
            if (z == 0) {
                bias0 = __ldg(b1 + cc);
                bias1 = __ldg(b1 + cc + 1);
            }
            if (r0 < M)
                *reinterpret_cast<__half2*>(Out + (size_t)r0 * HID + cc) =
                    __floats2half2_rn(acc[i][j][0] + bias0, acc[i][j][1] + bias1);
            if (r0 + 8 < M)
                *reinterpret_cast<__half2*>(Out + (size_t)(r0 + 8) * HID + cc) =
                    __floats2half2_rn(acc[i][j][2] + bias0, acc[i][j][3] + bias1);
        }
}

// ---------------------------------------------------------------------------
// Edge scoring: warp per edge slot (int32 indices), fp16 activations,
// b1 already folded into g_A.
// ---------------------------------------------------------------------------
__device__ __forceinline__ int clamp_idx(int v) {
    v = v < 0 ? 0 : v;
    return v >= NNODES ? NNODES - 1 : v;
}

__global__ __launch_bounds__(256)
void edge_score_kernel(const int* __restrict__ ei,
                       const int* __restrict__ nei,
                       const float* __restrict__ W2,
                       const float* __restrict__ b2,
                       float* __restrict__ out,
                       int E)
{
    const int lane = threadIdx.x & 31;
    const int warp = (blockIdx.x * blockDim.x + threadIdx.x) >> 5;
    if (warp >= 2 * E) return;

    float4 rw2a = *reinterpret_cast<const float4*>(W2 + lane * 8);
    float4 rw2b = *reinterpret_cast<const float4*>(W2 + lane * 8 + 4);
    float rw2[8] = {rw2a.x, rw2a.y, rw2a.z, rw2a.w, rw2b.x, rw2b.y, rw2b.z, rw2b.w};

    int s, d;
    if (warp < E) { s = ei[warp];       d = ei[E + warp]; }
    else          { s = nei[warp - E];  d = nei[E + (warp - E)]; }
    s = clamp_idx(s);
    d = clamp_idx(d);

    uint4 au = *reinterpret_cast<const uint4*>(g_A + (size_t)s * HID + lane * 8);
    uint4 bu = *reinterpret_cast<const uint4*>(g_B + (size_t)d * HID + lane * 8);
    const __half2* ah = reinterpret_cast<const __half2*>(&au);
    const __half2* bh = reinterpret_cast<const __half2*>(&bu);

    float acc = 0.f;
    #pragma unroll
    for (int q = 0; q < 4; q++) {
        float2 af = __half22float2(ah[q]);
        float2 bf = __half22float2(bh[q]);
        float v0 = af.x + bf.x;
        float v1 = af.y + bf.y;
        acc = fmaf(fmaxf(v0, 0.f), rw2[2*q],   acc);
        acc = fmaf(fmaxf(v1, 0.f), rw2[2*q+1], acc);
    }
    #pragma unroll
    for (int o = 16; o; o >>= 1)
        acc += __shfl_xor_sync(0xffffffffu, acc, o);

    if (lane == 0)
        out[warp] = acc + __ldg(b2);
}

// ---------------------------------------------------------------------------
extern "C" void kernel_launch(void* const* d_in, const int* in_sizes, int n_in,
                              void* d_out, int out_size)
{
    const float* x_src = (const float*)d_in[0];
    const float* x_dst = (const float*)d_in[1];
    const float* W1    = (const float*)d_in[2];   // [512, 256]
    const float* b1    = (const float*)d_in[3];
    const float* W2    = (const float*)d_in[4];   // [256, 1]
    const float* b2    = (const float*)d_in[5];
    const int*   ei    = (const int*)d_in[6];     // [2, E] int32
    const int*   nei   = (const int*)d_in[7];
    float*       out   = (float*)d_out;

    const int M = in_sizes[0] / D;       // 100000
    const int E = in_sizes[6] / 2;       // 262144

    cudaFuncSetAttribute(mma_gemm_kernel,
                         cudaFuncAttributeMaxDynamicSharedMemorySize, SMEMB);

    wprep_kernel<<<(2 * 256 * 256 + 255) / 256, 256>>>(W1);

    dim3 ggrd(HID / 128, (M + 127) / 128);
    mma_gemm_kernel<<<ggrd, 256, SMEMB>>>(x_src, b1, M, 0);
    mma_gemm_kernel<<<ggrd, 256, SMEMB>>>(x_dst, b1, M, 1);

    long long totalThreads = (long long)2 * E * 32;
    int threads = 256;
    int blocks  = (int)((totalThreads + threads - 1) / threads);
    edge_score_kernel<<<blocks, threads>>>(ei, nei, W2, b2, out, E);
}